// round 14
// baseline (speedup 1.0000x reference)
#include <cuda_runtime.h>
#include <cuda_fp16.h>
#include <cstdint>

// ---------------------------------------------------------------------------
// Problem constants
#define BDIM   64
#define NDIM   32
#define DDIM   512
#define NPAIR  992                 // 32*31 ordered pairs
#define MROWS  (BDIM * NPAIR)      // 63488 output rows
#define BNROWS (BDIM * NDIM)       // 2048 person rows

// Scratch (device globals; no allocations allowed)
__device__ __align__(16) unsigned short g_P[(size_t)BNROWS * 1024]; // fp16 partials (4 MB)
__device__ __align__(16) unsigned short g_Fh[BNROWS * 512];        // fp16 of F
__device__ __align__(16) unsigned short g_W1h[1024 * 512];         // fp16 W1 rearranged [c][k]
__device__ __align__(16) unsigned short g_W2h[512 * 512];          // fp16 of W2

// ---------------------------------------------------------------------------
// Helpers
// ---------------------------------------------------------------------------
__device__ __forceinline__ uint32_t smem_u32(const void* p) {
    uint32_t a;
    asm("{ .reg .u64 t; cvta.to.shared.u64 t, %1; cvt.u32.u64 %0, t; }"
        : "=r"(a) : "l"(p));
    return a;
}
__device__ __forceinline__ void ldsm_x4(uint32_t* r, uint32_t addr) {
    asm volatile("ldmatrix.sync.aligned.m8n8.x4.shared.b16 {%0,%1,%2,%3},[%4];"
        : "=r"(r[0]), "=r"(r[1]), "=r"(r[2]), "=r"(r[3]) : "r"(addr));
}
__device__ __forceinline__ void mma_f16(float* d, const uint32_t* a, const uint32_t* b) {
    asm volatile(
        "mma.sync.aligned.m16n8k16.row.col.f32.f16.f16.f32 "
        "{%0,%1,%2,%3},{%4,%5,%6,%7},{%8,%9},{%0,%1,%2,%3};"
        : "+f"(d[0]), "+f"(d[1]), "+f"(d[2]), "+f"(d[3])
        : "r"(a[0]), "r"(a[1]), "r"(a[2]), "r"(a[3]), "r"(b[0]), "r"(b[1]));
}
__device__ __forceinline__ void cp_async16(uint32_t dst, const void* src) {
    asm volatile("cp.async.cg.shared.global [%0], [%1], 16;"
        :: "r"(dst), "l"(__cvta_generic_to_global(src)) : "memory");
}
#define CP_COMMIT() asm volatile("cp.async.commit_group;" ::: "memory")
#define CP_WAIT(n)  asm volatile("cp.async.wait_group %0;" :: "n"(n) : "memory")

__device__ __forceinline__ uint2 f4_to_h4(float4 v) {
    __half2 a = __floats2half2_rn(v.x, v.y);
    __half2 b = __floats2half2_rn(v.z, v.w);
    return make_uint2(*reinterpret_cast<uint32_t*>(&a), *reinterpret_cast<uint32_t*>(&b));
}

// relu(a+b) on packed half2 (bit-identical to former k_hsplit math)
__device__ __forceinline__ uint32_t hrelu2(uint32_t u, uint32_t v) {
    __half2 a = *reinterpret_cast<__half2*>(&u);
    __half2 b = *reinterpret_cast<__half2*>(&v);
    __half2 s = __hmax2(__hadd2(a, b), __float2half2_rn(0.0f));
    return *reinterpret_cast<uint32_t*>(&s);
}

// ---------------------------------------------------------------------------
// k_prep: all input conversions in one launch.
// ---------------------------------------------------------------------------
__global__ __launch_bounds__(256)
void k_prep(const float* __restrict__ F, const float* __restrict__ W1,
            const float* __restrict__ W2)
{
    int idx = blockIdx.x * 256 + threadIdx.x;
    if (idx < 262144) {
        float4 v = reinterpret_cast<const float4*>(F)[idx];
        reinterpret_cast<uint2*>(g_Fh)[idx] = f4_to_h4(v);
    } else if (idx < 393216) {
        int i = idx - 262144;
        int L = i * 4;
        int c = L >> 9;
        int k = L & 511;
        float4 v = *reinterpret_cast<const float4*>(
            W1 + (size_t)(c & 511) * 1024 + ((c >> 9) << 9) + k);
        reinterpret_cast<uint2*>(g_W1h)[i] = f4_to_h4(v);
    } else {
        int i = idx - 393216;
        float4 v = reinterpret_cast<const float4*>(W2)[i];
        reinterpret_cast<uint2*>(g_W2h)[i] = f4_to_h4(v);
    }
}

// ---------------------------------------------------------------------------
// k_gemmA: P = F @ W1'^T (+ b1 on first 512 cols) -> fp16.
// M=2048, N=1024, K=512. CTA 128x128, 4 warps 2x2 of 64x64 warp tiles.
// 3-stage cp.async (A 16K | B 16K per stage). Single-buffered fragments.
// ---------------------------------------------------------------------------
#define STG      32768
#define SMEM_A3  (3 * STG + 1024)

__global__ __launch_bounds__(128, 2)
void k_gemmA(const unsigned short* __restrict__ A_g,
             const unsigned short* __restrict__ B_g,
             const float* __restrict__ bias,
             unsigned short* __restrict__ outP)
{
    extern __shared__ char dsm[];
    const int tid = threadIdx.x;
    const int wid = tid >> 5;
    const int lid = tid & 31;

    uint32_t raw = smem_u32(dsm);
    const uint32_t dbase = (raw + 1023u) & ~1023u;

    const int rowBase = blockIdx.y * 128;
    const int colBase = blockIdx.x * 128;

    const unsigned short* Asrc = A_g + (size_t)rowBase * 512;
    const unsigned short* Bsrc = B_g + (size_t)colBase * 512;

    auto ldt = [&](uint32_t dst, const unsigned short* src, int c) {
#pragma unroll
        for (int g = 0; g < 8; ++g) {
            const int q = tid + 128 * g;
            const int row = q >> 3;
            const int kb  = q & 7;
            const uint32_t off = (uint32_t)row * 128 + (uint32_t)((kb ^ (row & 7)) << 4);
            cp_async16(dst + off, src + (size_t)row * 512 + c * 64 + kb * 8);
        }
    };
    auto loadStage = [&](int c, int s) {
        const uint32_t st = dbase + s * STG;
        ldt(st,         Asrc, c);
        ldt(st + 16384, Bsrc, c);
    };

    const int wm = (wid & 1) * 64;
    const int wn = (wid >> 1) * 64;

    float acc[4][8][4];
#pragma unroll
    for (int mi = 0; mi < 4; ++mi)
#pragma unroll
        for (int ni = 0; ni < 8; ++ni)
#pragma unroll
            for (int q = 0; q < 4; ++q) acc[mi][ni][q] = 0.0f;

    const int mrow  = lid & 15;
    const int ksel  = lid >> 4;
    const int bn2   = lid & 7;
    const int khalf = (lid >> 3) & 1;
    const int tsel  = (lid >> 4) & 1;

    auto compute = [&](int s) {
        const uint32_t AhB = dbase + s * STG;
        const uint32_t BhB = AhB + 16384;
#pragma unroll
        for (int ks = 0; ks < 4; ++ks) {
            uint32_t ah[4][4], bh[8][2];
#pragma unroll
            for (int mi = 0; mi < 4; ++mi) {
                const uint32_t r = (uint32_t)(wm + mi * 16 + mrow);
                const uint32_t kb = (uint32_t)(ks * 2 + ksel);
                ldsm_x4(ah[mi], AhB + r * 128 + ((kb ^ (r & 7)) << 4));
            }
#pragma unroll
            for (int nip = 0; nip < 4; ++nip) {
                const uint32_t n = (uint32_t)(wn + (nip * 2 + tsel) * 8 + bn2);
                const uint32_t kb = (uint32_t)(ks * 2 + khalf);
                uint32_t t[4];
                ldsm_x4(t, BhB + n * 128 + ((kb ^ (n & 7)) << 4));
                bh[2 * nip][0] = t[0]; bh[2 * nip][1] = t[1];
                bh[2 * nip + 1][0] = t[2]; bh[2 * nip + 1][1] = t[3];
            }
#pragma unroll
            for (int mi = 0; mi < 4; ++mi)
#pragma unroll
                for (int ni = 0; ni < 8; ++ni)
                    mma_f16(acc[mi][ni], ah[mi], bh[ni]);
        }
    };

    loadStage(0, 0); CP_COMMIT();
    loadStage(1, 1); CP_COMMIT();

    for (int c = 0; c < 8; ++c) {
        CP_WAIT(1);
        __syncthreads();
        if (c + 2 < 8) loadStage(c + 2, (c + 2) % 3);
        CP_COMMIT();
        compute(c % 3);
    }

    // epilogue -> fp16 P
    {
        const int t2 = (lid & 3) * 2;
        const int gg = lid >> 2;
        float2 bb[8];
#pragma unroll
        for (int ni = 0; ni < 8; ++ni) {
            if (colBase < 512)
                bb[ni] = *reinterpret_cast<const float2*>(bias + colBase + wn + ni * 8 + t2);
            else
                bb[ni] = make_float2(0.f, 0.f);
        }
#pragma unroll
        for (int mi = 0; mi < 4; ++mi) {
            const int r0 = rowBase + wm + mi * 16 + gg;
#pragma unroll
            for (int ni = 0; ni < 8; ++ni) {
                const int cc = colBase + wn + ni * 8 + t2;
                __half2 h0 = __floats2half2_rn(acc[mi][ni][0] + bb[ni].x,
                                               acc[mi][ni][1] + bb[ni].y);
                __half2 h1 = __floats2half2_rn(acc[mi][ni][2] + bb[ni].x,
                                               acc[mi][ni][3] + bb[ni].y);
                *reinterpret_cast<uint32_t*>(outP + (size_t)r0 * 1024 + cc) =
                    *reinterpret_cast<uint32_t*>(&h0);
                *reinterpret_cast<uint32_t*>(outP + (size_t)(r0 + 8) * 1024 + cc) =
                    *reinterpret_cast<uint32_t*>(&h1);
            }
        }
    }
}

// ---------------------------------------------------------------------------
// k_gemmB_fused: out = relu(P1 + P2) @ W2h^T + b2, A produced in-kernel.
// M=63488, N=512, K=512. CTA 128x128, 4 warps 2x2 of 64x64 warp tiles.
// A: double-buffered 16KB smem, produced from L2-resident g_P by ALL threads
//    (thread t = row t; two 32-col groups interleaved with MMA half-blocks).
// B: 3-stage cp.async from g_W2h.
// smem: A0 16K | A1 16K | B0..B2 16K each = 80KB (+align). 2 CTAs/SM.
// ---------------------------------------------------------------------------
#define SMEM_FUSED (5 * 16384 + 1024)

__global__ __launch_bounds__(128, 2)
void k_gemmB_fused(const float* __restrict__ b2, float* __restrict__ out)
{
    extern __shared__ char dsm[];
    __shared__ int s_rowI[128], s_rowJ[128];

    const int tid = threadIdx.x;
    const int wid = tid >> 5;
    const int lid = tid & 31;

    uint32_t raw = smem_u32(dsm);
    const uint32_t dbase = (raw + 1023u) & ~1023u;
    char* dptr = dsm + (dbase - raw);

    const int rowBase = blockIdx.y * 128;
    const int colBase = blockIdx.x * 128;

    // pair -> P row offsets (halfword offsets)
    {
        int r = rowBase + tid;
        int b = r / NPAIR;
        int p = r - b * NPAIR;
        int i = p / 31;
        int jj = p - i * 31;
        int j = jj + (jj >= i ? 1 : 0);
        s_rowI[tid] = (b * NDIM + i) * 1024;
        s_rowJ[tid] = (b * NDIM + j) * 1024 + 512;
    }
    __syncthreads();

    const int rI = s_rowI[tid];
    const int rJ = s_rowJ[tid];
    const uint32_t rswz = (uint32_t)(tid & 7);
    const uint32_t rowOff = (uint32_t)tid * 128;

    // ---- A production: thread t = row t; group g covers cols g*32..g*32+31 ----
    auto loadGrp = [&](int c, int g, uint4* t1, uint4* t2) {
        const unsigned short* p1 = g_P + rI + c * 64 + g * 32;
        const unsigned short* p2 = g_P + rJ + c * 64 + g * 32;
#pragma unroll
        for (int q = 0; q < 4; ++q) {
            t1[q] = *reinterpret_cast<const uint4*>(p1 + q * 8);
            t2[q] = *reinterpret_cast<const uint4*>(p2 + q * 8);
        }
    };
    auto storeGrp = [&](char* Abuf, int g, const uint4* t1, const uint4* t2) {
#pragma unroll
        for (int q = 0; q < 4; ++q) {
            uint4 r;
            r.x = hrelu2(t1[q].x, t2[q].x);
            r.y = hrelu2(t1[q].y, t2[q].y);
            r.z = hrelu2(t1[q].z, t2[q].z);
            r.w = hrelu2(t1[q].w, t2[q].w);
            const uint32_t kb = (uint32_t)(g * 4 + q);
            *reinterpret_cast<uint4*>(Abuf + rowOff + ((kb ^ rswz) << 4)) = r;
        }
    };

    // ---- B loads (cp.async) ----
    const unsigned short* Bsrc = g_W2h + (size_t)colBase * 512;
    auto loadB = [&](int c, int s) {
        const uint32_t st = dbase + 32768 + (uint32_t)s * 16384;
#pragma unroll
        for (int g = 0; g < 8; ++g) {
            const int q = tid + 128 * g;
            const int row = q >> 3;
            const int kb  = q & 7;
            const uint32_t off = (uint32_t)row * 128 + (uint32_t)((kb ^ (row & 7)) << 4);
            cp_async16(st + off, Bsrc + (size_t)row * 512 + c * 64 + kb * 8);
        }
    };

    // ---- consumers ----
    const int wm = (wid & 1) * 64;
    const int wn = (wid >> 1) * 64;

    float acc[4][8][4];
#pragma unroll
    for (int mi = 0; mi < 4; ++mi)
#pragma unroll
        for (int ni = 0; ni < 8; ++ni)
#pragma unroll
            for (int q = 0; q < 4; ++q) acc[mi][ni][q] = 0.0f;

    const int mrow  = lid & 15;
    const int ksel  = lid >> 4;
    const int bn2   = lid & 7;
    const int khalf = (lid >> 3) & 1;
    const int tsel  = (lid >> 4) & 1;

    auto mma2ks = [&](uint32_t AhB, uint32_t BhB, int ks0) {
#pragma unroll
        for (int ks = ks0; ks < ks0 + 2; ++ks) {
            uint32_t ah[4][4], bh[8][2];
#pragma unroll
            for (int mi = 0; mi < 4; ++mi) {
                const uint32_t r = (uint32_t)(wm + mi * 16 + mrow);
                const uint32_t kb = (uint32_t)(ks * 2 + ksel);
                ldsm_x4(ah[mi], AhB + r * 128 + ((kb ^ (r & 7)) << 4));
            }
#pragma unroll
            for (int nip = 0; nip < 4; ++nip) {
                const uint32_t n = (uint32_t)(wn + (nip * 2 + tsel) * 8 + bn2);
                const uint32_t kb = (uint32_t)(ks * 2 + khalf);
                uint32_t t[4];
                ldsm_x4(t, BhB + n * 128 + ((kb ^ (n & 7)) << 4));
                bh[2 * nip][0] = t[0]; bh[2 * nip][1] = t[1];
                bh[2 * nip + 1][0] = t[2]; bh[2 * nip + 1][1] = t[3];
            }
#pragma unroll
            for (int mi = 0; mi < 4; ++mi)
#pragma unroll
                for (int ni = 0; ni < 8; ++ni)
                    mma_f16(acc[mi][ni], ah[mi], bh[ni]);
        }
    };

    // ---- prologue: produce A(0), prefetch B(0), B(1) ----
    {
        uint4 t1[4], t2[4];
        loadGrp(0, 0, t1, t2);
        storeGrp(dptr, 0, t1, t2);
        loadGrp(0, 1, t1, t2);
        storeGrp(dptr, 1, t1, t2);
    }
    loadB(0, 0); CP_COMMIT();
    loadB(1, 1); CP_COMMIT();

    // ---- main loop ----
    for (int c = 0; c < 8; ++c) {
        CP_WAIT(1);
        __syncthreads();                      // B(c) landed; A(c) STS visible
        if (c + 2 < 8) loadB(c + 2, (c + 2) % 3);
        CP_COMMIT();

        const uint32_t AhB = dbase + (uint32_t)(c & 1) * 16384;
        char* Anx = dptr + ((c + 1) & 1) * 16384;
        const uint32_t BhB = dbase + 32768 + (uint32_t)(c % 3) * 16384;

        uint4 t1[4], t2[4];
        const bool prod = (c < 7);
        if (prod) loadGrp(c + 1, 0, t1, t2);   // L2 loads hidden under MMAs
        mma2ks(AhB, BhB, 0);
        if (prod) {
            storeGrp(Anx, 0, t1, t2);
            loadGrp(c + 1, 1, t1, t2);
        }
        mma2ks(AhB, BhB, 2);
        if (prod) storeGrp(Anx, 1, t1, t2);
    }

    // ---- epilogue ----
    {
        const int t2 = (lid & 3) * 2;
        const int gg = lid >> 2;
        float2 bb[8];
#pragma unroll
        for (int ni = 0; ni < 8; ++ni)
            bb[ni] = *reinterpret_cast<const float2*>(b2 + colBase + wn + ni * 8 + t2);

#pragma unroll
        for (int mi = 0; mi < 4; ++mi) {
            const int r0 = rowBase + wm + mi * 16 + gg;
#pragma unroll
            for (int ni = 0; ni < 8; ++ni) {
                const int cc = colBase + wn + ni * 8 + t2;
                float2 v0, v1;
                v0.x = acc[mi][ni][0] + bb[ni].x;
                v0.y = acc[mi][ni][1] + bb[ni].y;
                v1.x = acc[mi][ni][2] + bb[ni].x;
                v1.y = acc[mi][ni][3] + bb[ni].y;
                *reinterpret_cast<float2*>(out + (size_t)r0 * 512 + cc) = v0;
                *reinterpret_cast<float2*>(out + (size_t)(r0 + 8) * 512 + cc) = v1;
            }
        }
    }
}

// ---------------------------------------------------------------------------
extern "C" void kernel_launch(void* const* d_in, const int* in_sizes, int n_in,
                              void* d_out, int out_size)
{
    const float* F  = (const float*)d_in[0];   // person_feats (64,32,512)
    const float* W1 = (const float*)d_in[1];   // (512, 1024)
    const float* b1 = (const float*)d_in[2];   // (512,)
    const float* W2 = (const float*)d_in[3];   // (512, 512)
    const float* b2 = (const float*)d_in[4];   // (512,)
    float* out = (float*)d_out;                // (64, 992, 512)

    cudaFuncSetAttribute(k_gemmA, cudaFuncAttributeMaxDynamicSharedMemorySize, SMEM_A3);
    cudaFuncSetAttribute(k_gemmB_fused, cudaFuncAttributeMaxDynamicSharedMemorySize, SMEM_FUSED);

    unsigned short *Fh, *W1h, *Ph;
    cudaGetSymbolAddress((void**)&Fh,  g_Fh);
    cudaGetSymbolAddress((void**)&W1h, g_W1h);
    cudaGetSymbolAddress((void**)&Ph,  g_P);

    // 1) convert inputs to fp16 in one launch
    k_prep<<<1792, 256>>>(F, W1, W2);

    // 2) P = F @ W1'^T (+ b1 on first 512 cols) -> fp16: M=2048, N=1024
    {
        dim3 g(8, 16);
        k_gemmA<<<g, 128, SMEM_A3>>>(Fh, W1h, b1, Ph);
    }

    // 3) out = relu(P1+P2) @ W2h^T + b2 (A produced in-kernel): M=63488, N=512
    {
        dim3 g(4, MROWS / 128);
        k_gemmB_fused<<<g, 128, SMEM_FUSED>>>(b2, out);
    }
}

// round 16
// speedup vs baseline: 1.1131x; 1.1131x over previous
#include <cuda_runtime.h>
#include <cuda_fp16.h>
#include <cstdint>

// ---------------------------------------------------------------------------
// Problem constants
#define BDIM   64
#define NDIM   32
#define DDIM   512
#define NPAIR  992                 // 32*31 ordered pairs
#define MROWS  (BDIM * NPAIR)      // 63488 output rows
#define BNROWS (BDIM * NDIM)       // 2048 person rows

// Scratch (device globals; no allocations allowed)
__device__ __align__(16) unsigned short g_P[(size_t)BNROWS * 1024]; // fp16 partials (4 MB)
__device__ __align__(16) unsigned short g_Fh[BNROWS * 512];        // fp16 of F
__device__ __align__(16) unsigned short g_W1h[1024 * 512];         // fp16 W1 rearranged [c][k]
__device__ __align__(16) unsigned short g_W2h[512 * 512];          // fp16 of W2
__device__ __align__(16) unsigned short g_Hh[(size_t)MROWS * 512]; // fp16 of H (65 MB)

// ---------------------------------------------------------------------------
// Helpers
// ---------------------------------------------------------------------------
__device__ __forceinline__ uint32_t smem_u32(const void* p) {
    uint32_t a;
    asm("{ .reg .u64 t; cvta.to.shared.u64 t, %1; cvt.u32.u64 %0, t; }"
        : "=r"(a) : "l"(p));
    return a;
}
__device__ __forceinline__ void ldsm_x4(uint32_t* r, uint32_t addr) {
    asm volatile("ldmatrix.sync.aligned.m8n8.x4.shared.b16 {%0,%1,%2,%3},[%4];"
        : "=r"(r[0]), "=r"(r[1]), "=r"(r[2]), "=r"(r[3]) : "r"(addr));
}
__device__ __forceinline__ void mma_f16(float* d, const uint32_t* a, const uint32_t* b) {
    asm volatile(
        "mma.sync.aligned.m16n8k16.row.col.f32.f16.f16.f32 "
        "{%0,%1,%2,%3},{%4,%5,%6,%7},{%8,%9},{%0,%1,%2,%3};"
        : "+f"(d[0]), "+f"(d[1]), "+f"(d[2]), "+f"(d[3])
        : "r"(a[0]), "r"(a[1]), "r"(a[2]), "r"(a[3]), "r"(b[0]), "r"(b[1]));
}
__device__ __forceinline__ void cp_async16(uint32_t dst, const void* src) {
    asm volatile("cp.async.cg.shared.global [%0], [%1], 16;"
        :: "r"(dst), "l"(__cvta_generic_to_global(src)) : "memory");
}
#define CP_COMMIT() asm volatile("cp.async.commit_group;" ::: "memory")
#define CP_WAIT(n)  asm volatile("cp.async.wait_group %0;" :: "n"(n) : "memory")

__device__ __forceinline__ uint2 f4_to_h4(float4 v) {
    __half2 a = __floats2half2_rn(v.x, v.y);
    __half2 b = __floats2half2_rn(v.z, v.w);
    return make_uint2(*reinterpret_cast<uint32_t*>(&a), *reinterpret_cast<uint32_t*>(&b));
}

// ---------------------------------------------------------------------------
// k_prep: all input conversions in one launch.
// ---------------------------------------------------------------------------
__global__ __launch_bounds__(256)
void k_prep(const float* __restrict__ F, const float* __restrict__ W1,
            const float* __restrict__ W2)
{
    int idx = blockIdx.x * 256 + threadIdx.x;
    if (idx < 262144) {
        float4 v = reinterpret_cast<const float4*>(F)[idx];
        reinterpret_cast<uint2*>(g_Fh)[idx] = f4_to_h4(v);
    } else if (idx < 393216) {
        int i = idx - 262144;
        int L = i * 4;
        int c = L >> 9;
        int k = L & 511;
        float4 v = *reinterpret_cast<const float4*>(
            W1 + (size_t)(c & 511) * 1024 + ((c >> 9) << 9) + k);
        reinterpret_cast<uint2*>(g_W1h)[i] = f4_to_h4(v);
    } else {
        int i = idx - 393216;
        float4 v = reinterpret_cast<const float4*>(W2)[i];
        reinterpret_cast<uint2*>(g_W2h)[i] = f4_to_h4(v);
    }
}

// ---------------------------------------------------------------------------
// H: H[r][k] = fp16(relu(P[b*32+i][k] + P[b*32+j][512+k]))  (P fp16)
// 8 warps per block, one row per warp, 16 elems per lane.
// ---------------------------------------------------------------------------
__global__ __launch_bounds__(256)
void k_hsplit()
{
    const int r   = blockIdx.x * 8 + (threadIdx.x >> 5);
    const int lid = threadIdx.x & 31;
    const int b = r / NPAIR;
    const int p = r - b * NPAIR;
    const int i = p / 31;
    const int jj = p - i * 31;
    const int j = jj + (jj >= i ? 1 : 0);

    const unsigned short* p1 = g_P + (size_t)(b * NDIM + i) * 1024 + lid * 16;
    const unsigned short* p2 = g_P + (size_t)(b * NDIM + j) * 1024 + 512 + lid * 16;
    unsigned short* hh = g_Hh + (size_t)r * 512 + lid * 16;

    const __half2 zero = __float2half2_rn(0.0f);
#pragma unroll
    for (int g = 0; g < 2; ++g) {
        uint4 u = *reinterpret_cast<const uint4*>(p1 + g * 8);
        uint4 v = *reinterpret_cast<const uint4*>(p2 + g * 8);
        uint4 H;
        const uint32_t* up = &u.x;
        const uint32_t* vp = &v.x;
        uint32_t* hp = &H.x;
#pragma unroll
        for (int q = 0; q < 4; ++q) {
            __half2 a = *reinterpret_cast<const __half2*>(&up[q]);
            __half2 c = *reinterpret_cast<const __half2*>(&vp[q]);
            __half2 s = __hmax2(__hadd2(a, c), zero);
            hp[q] = *reinterpret_cast<uint32_t*>(&s);
        }
        *reinterpret_cast<uint4*>(hh + g * 8) = H;
    }
}

// ---------------------------------------------------------------------------
// k_gemm16: single-term fp16 GEMM, fp32 accumulate.
//   out[r, n] = A[r,:] @ B[n,:] + bias
// CTA 128x128, 128 threads = 4 warps in 2(M)x2(N) grid of 64x64 warp tiles.
// K = 8 chunks of 64. TWO-stage cp.async (32KB/stage) -> 64KB/CTA -> 3 CTAs/SM.
// Single-buffered fragments (frag double-buffer measured neutral in R13).
// BIAS_MODE 1: bias only when colBase < 512 (gemmA). 2: always (gemmB).
// OUT_HALF 1: store fp16 (gemmA -> P). 0: store fp32.
// ---------------------------------------------------------------------------
#define STG      32768
#define SMEM_2S  (2 * STG + 1024)

template<int BIAS_MODE, int OUT_HALF>
__global__ __launch_bounds__(128, 3)
void k_gemm16(const unsigned short* __restrict__ A_g,
              const unsigned short* __restrict__ B_g,
              const float* __restrict__ bias,
              void* __restrict__ out_v, int outStride)
{
    extern __shared__ char dsm[];
    const int tid = threadIdx.x;
    const int wid = tid >> 5;
    const int lid = tid & 31;

    uint32_t raw = smem_u32(dsm);
    const uint32_t dbase = (raw + 1023u) & ~1023u;

    const int rowBase = blockIdx.y * 128;
    const int colBase = blockIdx.x * 128;

    const unsigned short* Asrc = A_g + (size_t)rowBase * 512;
    const unsigned short* Bsrc = B_g + (size_t)colBase * 512;

    auto ldt = [&](uint32_t dst, const unsigned short* src, int c) {
#pragma unroll
        for (int g = 0; g < 8; ++g) {
            const int q = tid + 128 * g;
            const int row = q >> 3;
            const int kb  = q & 7;
            const uint32_t off = (uint32_t)row * 128 + (uint32_t)((kb ^ (row & 7)) << 4);
            cp_async16(dst + off, src + (size_t)row * 512 + c * 64 + kb * 8);
        }
    };
    auto loadStage = [&](int c, int s) {
        const uint32_t st = dbase + s * STG;
        ldt(st,         Asrc, c);
        ldt(st + 16384, Bsrc, c);
    };

    const int wm = (wid & 1) * 64;
    const int wn = (wid >> 1) * 64;

    float acc[4][8][4];
#pragma unroll
    for (int mi = 0; mi < 4; ++mi)
#pragma unroll
        for (int ni = 0; ni < 8; ++ni)
#pragma unroll
            for (int q = 0; q < 4; ++q) acc[mi][ni][q] = 0.0f;

    const int mrow  = lid & 15;
    const int ksel  = lid >> 4;
    const int bn2   = lid & 7;
    const int khalf = (lid >> 3) & 1;
    const int tsel  = (lid >> 4) & 1;

    auto compute = [&](int s) {
        const uint32_t AhB = dbase + s * STG;
        const uint32_t BhB = AhB + 16384;
#pragma unroll
        for (int ks = 0; ks < 4; ++ks) {
            uint32_t ah[4][4], bh[8][2];
#pragma unroll
            for (int mi = 0; mi < 4; ++mi) {
                const uint32_t r = (uint32_t)(wm + mi * 16 + mrow);
                const uint32_t kb = (uint32_t)(ks * 2 + ksel);
                ldsm_x4(ah[mi], AhB + r * 128 + ((kb ^ (r & 7)) << 4));
            }
#pragma unroll
            for (int nip = 0; nip < 4; ++nip) {
                const uint32_t n = (uint32_t)(wn + (nip * 2 + tsel) * 8 + bn2);
                const uint32_t kb = (uint32_t)(ks * 2 + khalf);
                uint32_t t[4];
                ldsm_x4(t, BhB + n * 128 + ((kb ^ (n & 7)) << 4));
                bh[2 * nip][0] = t[0]; bh[2 * nip][1] = t[1];
                bh[2 * nip + 1][0] = t[2]; bh[2 * nip + 1][1] = t[3];
            }
#pragma unroll
            for (int mi = 0; mi < 4; ++mi)
#pragma unroll
                for (int ni = 0; ni < 8; ++ni)
                    mma_f16(acc[mi][ni], ah[mi], bh[ni]);
        }
    };

    // 2-stage pipeline: stages 0,1 in flight; reload stage c&1 after compute(c).
    loadStage(0, 0); CP_COMMIT();
    loadStage(1, 1); CP_COMMIT();

    for (int c = 0; c < 8; ++c) {
        CP_WAIT(1);                    // chunk c landed
        __syncthreads();
        compute(c & 1);
        __syncthreads();               // all warps done reading stage c&1
        if (c + 2 < 8) loadStage(c + 2, c & 1);
        CP_COMMIT();                   // empty group when no loads (uniform count)
    }

    // epilogue
    {
        const int t2 = (lid & 3) * 2;
        const int gg = lid >> 2;
        float2 bb[8];
#pragma unroll
        for (int ni = 0; ni < 8; ++ni) {
            if (BIAS_MODE == 2 || colBase < 512)
                bb[ni] = *reinterpret_cast<const float2*>(bias + colBase + wn + ni * 8 + t2);
            else
                bb[ni] = make_float2(0.f, 0.f);
        }
#pragma unroll
        for (int mi = 0; mi < 4; ++mi) {
            const int r0 = rowBase + wm + mi * 16 + gg;
#pragma unroll
            for (int ni = 0; ni < 8; ++ni) {
                const int cc = colBase + wn + ni * 8 + t2;
                float2 v0, v1;
                v0.x = acc[mi][ni][0] + bb[ni].x;
                v0.y = acc[mi][ni][1] + bb[ni].y;
                v1.x = acc[mi][ni][2] + bb[ni].x;
                v1.y = acc[mi][ni][3] + bb[ni].y;
                if (OUT_HALF) {
                    unsigned short* o16 = (unsigned short*)out_v;
                    __half2 h0 = __floats2half2_rn(v0.x, v0.y);
                    __half2 h1 = __floats2half2_rn(v1.x, v1.y);
                    *reinterpret_cast<uint32_t*>(o16 + (size_t)r0 * outStride + cc) =
                        *reinterpret_cast<uint32_t*>(&h0);
                    *reinterpret_cast<uint32_t*>(o16 + (size_t)(r0 + 8) * outStride + cc) =
                        *reinterpret_cast<uint32_t*>(&h1);
                } else {
                    float* o32 = (float*)out_v;
                    *reinterpret_cast<float2*>(o32 + (size_t)r0 * outStride + cc) = v0;
                    *reinterpret_cast<float2*>(o32 + (size_t)(r0 + 8) * outStride + cc) = v1;
                }
            }
        }
    }
}

// ---------------------------------------------------------------------------
extern "C" void kernel_launch(void* const* d_in, const int* in_sizes, int n_in,
                              void* d_out, int out_size)
{
    const float* F  = (const float*)d_in[0];   // person_feats (64,32,512)
    const float* W1 = (const float*)d_in[1];   // (512, 1024)
    const float* b1 = (const float*)d_in[2];   // (512,)
    const float* W2 = (const float*)d_in[3];   // (512, 512)
    const float* b2 = (const float*)d_in[4];   // (512,)
    float* out = (float*)d_out;                // (64, 992, 512)

    cudaFuncSetAttribute(k_gemm16<1,1>, cudaFuncAttributeMaxDynamicSharedMemorySize, SMEM_2S);
    cudaFuncSetAttribute(k_gemm16<2,0>, cudaFuncAttributeMaxDynamicSharedMemorySize, SMEM_2S);

    unsigned short *Fh, *W1h, *W2h, *Hh, *Ph;
    cudaGetSymbolAddress((void**)&Fh,  g_Fh);
    cudaGetSymbolAddress((void**)&W1h, g_W1h);
    cudaGetSymbolAddress((void**)&W2h, g_W2h);
    cudaGetSymbolAddress((void**)&Hh,  g_Hh);
    cudaGetSymbolAddress((void**)&Ph,  g_P);

    // 1) convert all inputs to fp16 in one launch
    k_prep<<<1792, 256>>>(F, W1, W2);

    // 2) P = F @ W1'^T (+ b1 on first 512 cols) -> fp16: M=2048, N=1024
    {
        dim3 g(8, 16);
        k_gemm16<1,1><<<g, 128, SMEM_2S>>>(Fh, W1h, b1, Ph, 1024);
    }

    // 3) H = fp16(relu(P1 + P2))
    k_hsplit<<<MROWS / 8, 256>>>();

    // 4) out = Hh @ W2h^T + b2: M=63488, N=512
    {
        dim3 g(4, MROWS / 128);
        k_gemm16<2,0><<<g, 128, SMEM_2S>>>(Hh, W2h, b2, out, 512);
    }
}

// round 17
// speedup vs baseline: 1.2731x; 1.1437x over previous
#include <cuda_runtime.h>
#include <cuda_fp16.h>
#include <cstdint>

// ---------------------------------------------------------------------------
// Problem constants
#define BDIM   64
#define NDIM   32
#define DDIM   512
#define NPAIR  992                 // 32*31 ordered pairs
#define MROWS  (BDIM * NPAIR)      // 63488 output rows
#define BNROWS (BDIM * NDIM)       // 2048 person rows

// Scratch (device globals; no allocations allowed)
__device__ __align__(16) unsigned short g_P[(size_t)BNROWS * 1024]; // fp16 partials (4 MB)
__device__ __align__(16) unsigned short g_Fh[BNROWS * 512];        // fp16 of F
__device__ __align__(16) unsigned short g_W1h[1024 * 512];         // fp16 W1 rearranged [c][k]
__device__ __align__(16) unsigned short g_W2h[512 * 512];          // fp16 of W2
__device__ __align__(16) unsigned short g_Hh[(size_t)MROWS * 512]; // fp16 of H (65 MB)

// ---------------------------------------------------------------------------
// Helpers
// ---------------------------------------------------------------------------
__device__ __forceinline__ uint32_t smem_u32(const void* p) {
    uint32_t a;
    asm("{ .reg .u64 t; cvta.to.shared.u64 t, %1; cvt.u32.u64 %0, t; }"
        : "=r"(a) : "l"(p));
    return a;
}
__device__ __forceinline__ void ldsm_x4(uint32_t* r, uint32_t addr) {
    asm volatile("ldmatrix.sync.aligned.m8n8.x4.shared.b16 {%0,%1,%2,%3},[%4];"
        : "=r"(r[0]), "=r"(r[1]), "=r"(r[2]), "=r"(r[3]) : "r"(addr));
}
__device__ __forceinline__ void mma_f16(float* d, const uint32_t* a, const uint32_t* b) {
    asm volatile(
        "mma.sync.aligned.m16n8k16.row.col.f32.f16.f16.f32 "
        "{%0,%1,%2,%3},{%4,%5,%6,%7},{%8,%9},{%0,%1,%2,%3};"
        : "+f"(d[0]), "+f"(d[1]), "+f"(d[2]), "+f"(d[3])
        : "r"(a[0]), "r"(a[1]), "r"(a[2]), "r"(a[3]), "r"(b[0]), "r"(b[1]));
}
__device__ __forceinline__ void cp_async16(uint32_t dst, const void* src) {
    asm volatile("cp.async.cg.shared.global [%0], [%1], 16;"
        :: "r"(dst), "l"(__cvta_generic_to_global(src)) : "memory");
}
#define CP_COMMIT() asm volatile("cp.async.commit_group;" ::: "memory")
#define CP_WAIT(n)  asm volatile("cp.async.wait_group %0;" :: "n"(n) : "memory")

__device__ __forceinline__ uint2 f4_to_h4(float4 v) {
    __half2 a = __floats2half2_rn(v.x, v.y);
    __half2 b = __floats2half2_rn(v.z, v.w);
    return make_uint2(*reinterpret_cast<uint32_t*>(&a), *reinterpret_cast<uint32_t*>(&b));
}

// ---------------------------------------------------------------------------
// k_prep: all input conversions in one launch.
// ---------------------------------------------------------------------------
__global__ __launch_bounds__(256)
void k_prep(const float* __restrict__ F, const float* __restrict__ W1,
            const float* __restrict__ W2)
{
    int idx = blockIdx.x * 256 + threadIdx.x;
    if (idx < 262144) {
        float4 v = reinterpret_cast<const float4*>(F)[idx];
        reinterpret_cast<uint2*>(g_Fh)[idx] = f4_to_h4(v);
    } else if (idx < 393216) {
        int i = idx - 262144;
        int L = i * 4;
        int c = L >> 9;
        int k = L & 511;
        float4 v = *reinterpret_cast<const float4*>(
            W1 + (size_t)(c & 511) * 1024 + ((c >> 9) << 9) + k);
        reinterpret_cast<uint2*>(g_W1h)[i] = f4_to_h4(v);
    } else {
        int i = idx - 393216;
        float4 v = reinterpret_cast<const float4*>(W2)[i];
        reinterpret_cast<uint2*>(g_W2h)[i] = f4_to_h4(v);
    }
}

// ---------------------------------------------------------------------------
// H: H[r][k] = fp16(relu(P[b*32+i][k] + P[b*32+j][512+k]))  (P fp16)
// 8 warps per block, one row per warp, 16 elems per lane.
// ---------------------------------------------------------------------------
__global__ __launch_bounds__(256)
void k_hsplit()
{
    const int r   = blockIdx.x * 8 + (threadIdx.x >> 5);
    const int lid = threadIdx.x & 31;
    const int b = r / NPAIR;
    const int p = r - b * NPAIR;
    const int i = p / 31;
    const int jj = p - i * 31;
    const int j = jj + (jj >= i ? 1 : 0);

    const unsigned short* p1 = g_P + (size_t)(b * NDIM + i) * 1024 + lid * 16;
    const unsigned short* p2 = g_P + (size_t)(b * NDIM + j) * 1024 + 512 + lid * 16;
    unsigned short* hh = g_Hh + (size_t)r * 512 + lid * 16;

    const __half2 zero = __float2half2_rn(0.0f);
#pragma unroll
    for (int g = 0; g < 2; ++g) {
        uint4 u = *reinterpret_cast<const uint4*>(p1 + g * 8);
        uint4 v = *reinterpret_cast<const uint4*>(p2 + g * 8);
        uint4 H;
        const uint32_t* up = &u.x;
        const uint32_t* vp = &v.x;
        uint32_t* hp = &H.x;
#pragma unroll
        for (int q = 0; q < 4; ++q) {
            __half2 a = *reinterpret_cast<const __half2*>(&up[q]);
            __half2 c = *reinterpret_cast<const __half2*>(&vp[q]);
            __half2 s = __hmax2(__hadd2(a, c), zero);
            hp[q] = *reinterpret_cast<uint32_t*>(&s);
        }
        *reinterpret_cast<uint4*>(hh + g * 8) = H;
    }
}

// ---------------------------------------------------------------------------
// k_gemm16: single-term fp16 GEMM, fp32 accumulate. (R11-proven config)
//   out[r, n] = A[r,:] @ B[n,:] + bias
// CTA 128x128, 128 threads = 4 warps in 2(M)x2(N) grid of 64x64 warp tiles.
// K = 8 chunks of 64. THREE-stage cp.async (32KB/stage) -> 96KB/CTA, 2 CTAs/SM.
// Single-buffered fragments, registers unconstrained (R11 measured 103.3us).
// BIAS_MODE 1: bias only when colBase < 512 (gemmA). 2: always (gemmB).
// OUT_HALF 1: store fp16 (gemmA -> P). 0: store fp32.
// ---------------------------------------------------------------------------
#define STG      32768
#define SMEM_3S  (3 * STG + 1024)

template<int BIAS_MODE, int OUT_HALF>
__global__ __launch_bounds__(128, 2)
void k_gemm16(const unsigned short* __restrict__ A_g,
              const unsigned short* __restrict__ B_g,
              const float* __restrict__ bias,
              void* __restrict__ out_v, int outStride)
{
    extern __shared__ char dsm[];
    const int tid = threadIdx.x;
    const int wid = tid >> 5;
    const int lid = tid & 31;

    uint32_t raw = smem_u32(dsm);
    const uint32_t dbase = (raw + 1023u) & ~1023u;

    const int rowBase = blockIdx.y * 128;
    const int colBase = blockIdx.x * 128;

    const unsigned short* Asrc = A_g + (size_t)rowBase * 512;
    const unsigned short* Bsrc = B_g + (size_t)colBase * 512;

    auto ldt = [&](uint32_t dst, const unsigned short* src, int c) {
#pragma unroll
        for (int g = 0; g < 8; ++g) {
            const int q = tid + 128 * g;
            const int row = q >> 3;
            const int kb  = q & 7;
            const uint32_t off = (uint32_t)row * 128 + (uint32_t)((kb ^ (row & 7)) << 4);
            cp_async16(dst + off, src + (size_t)row * 512 + c * 64 + kb * 8);
        }
    };
    auto loadStage = [&](int c, int s) {
        const uint32_t st = dbase + s * STG;
        ldt(st,         Asrc, c);
        ldt(st + 16384, Bsrc, c);
    };

    const int wm = (wid & 1) * 64;
    const int wn = (wid >> 1) * 64;

    float acc[4][8][4];
#pragma unroll
    for (int mi = 0; mi < 4; ++mi)
#pragma unroll
        for (int ni = 0; ni < 8; ++ni)
#pragma unroll
            for (int q = 0; q < 4; ++q) acc[mi][ni][q] = 0.0f;

    const int mrow  = lid & 15;
    const int ksel  = lid >> 4;
    const int bn2   = lid & 7;
    const int khalf = (lid >> 3) & 1;
    const int tsel  = (lid >> 4) & 1;

    auto compute = [&](int s) {
        const uint32_t AhB = dbase + s * STG;
        const uint32_t BhB = AhB + 16384;
#pragma unroll
        for (int ks = 0; ks < 4; ++ks) {
            uint32_t ah[4][4], bh[8][2];
#pragma unroll
            for (int mi = 0; mi < 4; ++mi) {
                const uint32_t r = (uint32_t)(wm + mi * 16 + mrow);
                const uint32_t kb = (uint32_t)(ks * 2 + ksel);
                ldsm_x4(ah[mi], AhB + r * 128 + ((kb ^ (r & 7)) << 4));
            }
#pragma unroll
            for (int nip = 0; nip < 4; ++nip) {
                const uint32_t n = (uint32_t)(wn + (nip * 2 + tsel) * 8 + bn2);
                const uint32_t kb = (uint32_t)(ks * 2 + khalf);
                uint32_t t[4];
                ldsm_x4(t, BhB + n * 128 + ((kb ^ (n & 7)) << 4));
                bh[2 * nip][0] = t[0]; bh[2 * nip][1] = t[1];
                bh[2 * nip + 1][0] = t[2]; bh[2 * nip + 1][1] = t[3];
            }
#pragma unroll
            for (int mi = 0; mi < 4; ++mi)
#pragma unroll
                for (int ni = 0; ni < 8; ++ni)
                    mma_f16(acc[mi][ni], ah[mi], bh[ni]);
        }
    };

    // 3-stage pipeline (R11-proven): prefetch 2 ahead, load before compute.
    loadStage(0, 0); CP_COMMIT();
    loadStage(1, 1); CP_COMMIT();

    for (int c = 0; c < 8; ++c) {
        CP_WAIT(1);
        __syncthreads();
        if (c + 2 < 8) loadStage(c + 2, (c + 2) % 3);
        CP_COMMIT();
        compute(c % 3);
    }

    // epilogue
    {
        const int t2 = (lid & 3) * 2;
        const int gg = lid >> 2;
        float2 bb[8];
#pragma unroll
        for (int ni = 0; ni < 8; ++ni) {
            if (BIAS_MODE == 2 || colBase < 512)
                bb[ni] = *reinterpret_cast<const float2*>(bias + colBase + wn + ni * 8 + t2);
            else
                bb[ni] = make_float2(0.f, 0.f);
        }
#pragma unroll
        for (int mi = 0; mi < 4; ++mi) {
            const int r0 = rowBase + wm + mi * 16 + gg;
#pragma unroll
            for (int ni = 0; ni < 8; ++ni) {
                const int cc = colBase + wn + ni * 8 + t2;
                float2 v0, v1;
                v0.x = acc[mi][ni][0] + bb[ni].x;
                v0.y = acc[mi][ni][1] + bb[ni].y;
                v1.x = acc[mi][ni][2] + bb[ni].x;
                v1.y = acc[mi][ni][3] + bb[ni].y;
                if (OUT_HALF) {
                    unsigned short* o16 = (unsigned short*)out_v;
                    __half2 h0 = __floats2half2_rn(v0.x, v0.y);
                    __half2 h1 = __floats2half2_rn(v1.x, v1.y);
                    *reinterpret_cast<uint32_t*>(o16 + (size_t)r0 * outStride + cc) =
                        *reinterpret_cast<uint32_t*>(&h0);
                    *reinterpret_cast<uint32_t*>(o16 + (size_t)(r0 + 8) * outStride + cc) =
                        *reinterpret_cast<uint32_t*>(&h1);
                } else {
                    float* o32 = (float*)out_v;
                    *reinterpret_cast<float2*>(o32 + (size_t)r0 * outStride + cc) = v0;
                    *reinterpret_cast<float2*>(o32 + (size_t)(r0 + 8) * outStride + cc) = v1;
                }
            }
        }
    }
}

// ---------------------------------------------------------------------------
extern "C" void kernel_launch(void* const* d_in, const int* in_sizes, int n_in,
                              void* d_out, int out_size)
{
    const float* F  = (const float*)d_in[0];   // person_feats (64,32,512)
    const float* W1 = (const float*)d_in[1];   // (512, 1024)
    const float* b1 = (const float*)d_in[2];   // (512,)
    const float* W2 = (const float*)d_in[3];   // (512, 512)
    const float* b2 = (const float*)d_in[4];   // (512,)
    float* out = (float*)d_out;                // (64, 992, 512)

    cudaFuncSetAttribute(k_gemm16<1,1>, cudaFuncAttributeMaxDynamicSharedMemorySize, SMEM_3S);
    cudaFuncSetAttribute(k_gemm16<2,0>, cudaFuncAttributeMaxDynamicSharedMemorySize, SMEM_3S);

    unsigned short *Fh, *W1h, *W2h, *Hh, *Ph;
    cudaGetSymbolAddress((void**)&Fh,  g_Fh);
    cudaGetSymbolAddress((void**)&W1h, g_W1h);
    cudaGetSymbolAddress((void**)&W2h, g_W2h);
    cudaGetSymbolAddress((void**)&Hh,  g_Hh);
    cudaGetSymbolAddress((void**)&Ph,  g_P);

    // 1) convert all inputs to fp16 in one launch
    k_prep<<<1792, 256>>>(F, W1, W2);

    // 2) P = F @ W1'^T (+ b1 on first 512 cols) -> fp16: M=2048, N=1024
    {
        dim3 g(8, 16);
        k_gemm16<1,1><<<g, 128, SMEM_3S>>>(Fh, W1h, b1, Ph, 1024);
    }

    // 3) H = fp16(relu(P1 + P2))
    k_hsplit<<<MROWS / 8, 256>>>();

    // 4) out = Hh @ W2h^T + b2: M=63488, N=512
    {
        dim3 g(4, MROWS / 128);
        k_gemm16<2,0><<<g, 128, SMEM_3S>>>(Hh, W2h, b2, out, 512);
    }
}